// round 1
// baseline (speedup 1.0000x reference)
#include <cuda_runtime.h>
#include <cuda_bf16.h>
#include <math.h>
#include <stdint.h>

#define NCLS 80
#define BB   32
#define TT   64
#define HW4  (80*80)
#define HW5  (40*40)

// scratch (no allocations allowed)
__device__ unsigned char g_obj4[BB*HW4];
__device__ unsigned char g_obj5[BB*HW5];
// 0 lb, 1 lo_targets, 2 lc, 3 n, 4 bgsum4, 5 bgsum5
__device__ float g_accf[6];
__device__ int   g_bgcnt[2];

__device__ __forceinline__ float softplusf(float x) {
    return fmaxf(x, 0.f) + log1pf(expf(-fabsf(x)));
}

__global__ void k_zero() {
    int i = blockIdx.x * blockDim.x + threadIdx.x;
    int stride = gridDim.x * blockDim.x;
    uint32_t* o4 = reinterpret_cast<uint32_t*>(g_obj4);
    uint32_t* o5 = reinterpret_cast<uint32_t*>(g_obj5);
    const int n4 = (BB*HW4)/4, n5 = (BB*HW5)/4;
    for (int j = i; j < n4; j += stride) o4[j] = 0u;
    for (int j = i; j < n5; j += stride) o5[j] = 0u;
    if (i < 6) g_accf[i] = 0.f;
    if (i < 2) g_bgcnt[i] = 0;
}

// one warp per target
__global__ void k_targets(const float* __restrict__ cls4, const float* __restrict__ reg4,
                          const float* __restrict__ cls5, const float* __restrict__ reg5,
                          const int*   __restrict__ t4c,  const float* __restrict__ t4b,
                          const float* __restrict__ t4m,
                          const int*   __restrict__ t5c,  const float* __restrict__ t5b,
                          const float* __restrict__ t5m)
{
    int w    = (blockIdx.x * blockDim.x + threadIdx.x) >> 5;
    int lane = threadIdx.x & 31;
    if (w >= 2 * BB * TT) return;

    int scale = (w >= BB * TT) ? 1 : 0;
    int idx   = w - scale * BB * TT;      // b*TT + t
    int b     = idx / TT;

    const float* cls = scale ? cls5 : cls4;
    const float* reg = scale ? reg5 : reg4;
    const int*   tc  = scale ? t5c  : t4c;
    const float* tb  = scale ? t5b  : t4b;
    const float* tm  = scale ? t5m  : t4m;
    unsigned char* obj = scale ? g_obj5 : g_obj4;
    const int S  = scale ? 40 : 80;
    const int HW = S * S;

    float mask = tm[idx];
    int   cid  = tc[idx];
    float bx = tb[idx*4+0], by = tb[idx*4+1], bw = tb[idx*4+2], bh = tb[idx*4+3];

    float tx = bx * (float)S, ty = by * (float)S;
    float tw = bw * (float)S, th = bh * (float)S;
    float txc = fminf(fmaxf(tx, 0.f), (float)(S-1));
    float tyc = fminf(fmaxf(ty, 0.f), (float)(S-1));
    int gx = (int)txc, gy = (int)tyc;
    int cell = gy * S + gx;

    const float* cbase = cls + (size_t)b * (NCLS+1) * HW + cell;
    const float* rbase = reg + (size_t)b * 4 * HW + cell;

    // focal loss over 80 classes, 3 classes per lane
    float fsum = 0.f;
    #pragma unroll
    for (int k = 0; k < 3; k++) {
        int c = lane + 32*k;
        if (c < NCLS) {
            float x   = cbase[(size_t)(1 + c) * HW];
            float tgt = (c == cid) ? 1.f : 0.f;
            float bce = softplusf(x) - x * tgt;
            float p   = 1.f / (1.f + expf(-x));
            float pt  = (tgt > 0.f) ? p : (1.f - p);
            float om  = 1.f - pt;
            fsum += 0.25f * om * om * bce;  // ALPHA=0.25, GAMMA=2
        }
    }
    #pragma unroll
    for (int o = 16; o; o >>= 1) fsum += __shfl_xor_sync(0xffffffffu, fsum, o);

    if (lane == 0) {
        float rv0 = rbase[0];
        float rv1 = rbase[HW];
        float rv2 = rbase[2*HW];
        float rv3 = rbase[3*HW];
        float dx = 1.f / (1.f + expf(-rv0));
        float dy = 1.f / (1.f + expf(-rv1));
        float dw = expf(fminf(fmaxf(rv2, -4.f), 4.f));
        float dh = expf(fminf(fmaxf(rv3, -4.f), 4.f));
        float px = (float)gx + dx, py = (float)gy + dy;

        float d0 = (px - 0.5f*dw) - (tx - 0.5f*tw);
        float d1 = (py - 0.5f*dh) - (ty - 0.5f*th);
        float d2 = (px + 0.5f*dw) - (tx + 0.5f*tw);
        float d3 = (py + 0.5f*dh) - (ty + 0.5f*th);
        float sl1 = 0.f;
        {
            float a;
            a = fabsf(d0); sl1 += (a < 1.f) ? 0.5f*d0*d0 : a - 0.5f;
            a = fabsf(d1); sl1 += (a < 1.f) ? 0.5f*d1*d1 : a - 0.5f;
            a = fabsf(d2); sl1 += (a < 1.f) ? 0.5f*d2*d2 : a - 0.5f;
            a = fabsf(d3); sl1 += (a < 1.f) ? 0.5f*d3*d3 : a - 0.5f;
        }
        sl1 *= 0.25f;

        float obj_t = cbase[0];
        float lo    = softplusf(-obj_t);

        atomicAdd(&g_accf[0], sl1 * mask);
        atomicAdd(&g_accf[1], lo * mask);
        atomicAdd(&g_accf[2], (fsum * (1.f / (float)NCLS)) * mask);
        atomicAdd(&g_accf[3], mask);
        if (mask > 0.f) obj[b * HW + cell] = 1;
    }
}

__global__ void k_bg(const float* __restrict__ cls4, const float* __restrict__ cls5)
{
    int tid = blockIdx.x * blockDim.x + threadIdx.x;
    int stride = gridDim.x * blockDim.x;
    const int N4 = BB * HW4, N5 = BB * HW5;

    float s4 = 0.f, s5 = 0.f;
    int   c4 = 0,   c5 = 0;

    for (int i = tid; i < N4; i += stride) {
        if (g_obj4[i] == 0) {
            int b = i / HW4, cell = i - b * HW4;
            float x = cls4[(size_t)b * (NCLS+1) * HW4 + cell];
            s4 += softplusf(x);
            c4++;
        }
    }
    for (int i = tid; i < N5; i += stride) {
        if (g_obj5[i] == 0) {
            int b = i / HW5, cell = i - b * HW5;
            float x = cls5[(size_t)b * (NCLS+1) * HW5 + cell];
            s5 += softplusf(x);
            c5++;
        }
    }

    // warp reduce, then one atomic per warp
    #pragma unroll
    for (int o = 16; o; o >>= 1) {
        s4 += __shfl_xor_sync(0xffffffffu, s4, o);
        s5 += __shfl_xor_sync(0xffffffffu, s5, o);
        c4 += __shfl_xor_sync(0xffffffffu, c4, o);
        c5 += __shfl_xor_sync(0xffffffffu, c5, o);
    }
    if ((threadIdx.x & 31) == 0) {
        if (s4 != 0.f) atomicAdd(&g_accf[4], s4);
        if (s5 != 0.f) atomicAdd(&g_accf[5], s5);
        if (c4)        atomicAdd(&g_bgcnt[0], c4);
        if (c5)        atomicAdd(&g_bgcnt[1], c5);
    }
}

__global__ void k_final(float* __restrict__ out)
{
    float lb  = g_accf[0];
    float lo  = g_accf[1];
    float lc  = g_accf[2];
    float n   = g_accf[3];
    float bg4 = g_accf[4];
    float bg5 = g_accf[5];
    int   c4  = g_bgcnt[0];
    int   c5  = g_bgcnt[1];

    // per-scale background term folded into lo (matches per-scale computation)
    lo += 0.05f * ((c4 > 0) ? bg4 / (float)(c4 > 1 ? c4 : 1) : 0.f);
    lo += 0.05f * ((c5 > 0) ? bg5 / (float)(c5 > 1 ? c5 : 1) : 0.f);

    if (n > 0.f) {
        float dn = fmaxf(n, 1.f);
        lb /= dn;
        lc /= dn;
    }
    lo /= fmaxf(n, 1.f);

    out[0] = 2.0f * lb + 1.0f * lo + 0.5f * lc;
}

extern "C" void kernel_launch(void* const* d_in, const int* in_sizes, int n_in,
                              void* d_out, int out_size)
{
    const float* cls4 = (const float*)d_in[0];
    const float* reg4 = (const float*)d_in[1];
    const float* cls5 = (const float*)d_in[2];
    const float* reg5 = (const float*)d_in[3];
    const int*   t4c  = (const int*)  d_in[4];
    const float* t4b  = (const float*)d_in[5];
    const float* t4m  = (const float*)d_in[6];
    const int*   t5c  = (const int*)  d_in[7];
    const float* t5b  = (const float*)d_in[8];
    const float* t5m  = (const float*)d_in[9];
    float* out = (float*)d_out;

    k_zero<<<256, 256>>>();
    // 2*32*64 = 4096 warps -> 131072 threads
    k_targets<<<512, 256>>>(cls4, reg4, cls5, reg5, t4c, t4b, t4m, t5c, t5b, t5m);
    k_bg<<<592, 256>>>(cls4, cls5);
    k_final<<<1, 1>>>(out);
}

// round 2
// speedup vs baseline: 2.3936x; 2.3936x over previous
#include <cuda_runtime.h>
#include <cuda_bf16.h>
#include <math.h>
#include <stdint.h>

#define NCLS 80
#define BB   32
#define TT   64
#define HW4  (80*80)
#define HW5  (40*40)
#define NT   (BB*TT)          // targets per scale = 2048
#define GRID 512
#define BLK  256

// ---- persistent device scratch (zero-initialized at load; kernel restores zeros) ----
__device__ uint32_t g_map4[BB*HW4];   // hit map scale 4 (0 or 1)
__device__ uint32_t g_map5[BB*HW5];   // hit map scale 5
__device__ uint32_t g_list[2*NT];     // encoded hit cells for cleanup
// floats: 0 lb, 1 lo, 2 lc, 3 n, 4 tot4, 5 tot5, 6 corr4, 7 corr5
__device__ float    g_accf[8];
__device__ int      g_hit[2];         // distinct hit cells per scale
__device__ int      g_len;            // hit list length
__device__ unsigned g_done;           // finished-block counter

__device__ __forceinline__ float softplusf(float x) {
    return fmaxf(x, 0.f) + log1pf(__expf(-fabsf(x)));
}

__global__ __launch_bounds__(BLK)
void k_all(const float* __restrict__ cls4, const float* __restrict__ reg4,
           const float* __restrict__ cls5, const float* __restrict__ reg5,
           const int*   __restrict__ t4c,  const float* __restrict__ t4b,
           const float* __restrict__ t4m,
           const int*   __restrict__ t5c,  const float* __restrict__ t5b,
           const float* __restrict__ t5m,
           float* __restrict__ out)
{
    __shared__ float sacc[8];
    __shared__ int   shit[2];
    __shared__ bool  isLast;

    int tid  = threadIdx.x;
    int lane = tid & 31;
    if (tid < 8) sacc[tid] = 0.f;
    if (tid < 2) shit[tid] = 0;
    __syncthreads();

    // ---------------- per-target losses (one warp per target) ----------------
    {
        int w = blockIdx.x * (BLK >> 5) + (tid >> 5);   // 0..4095
        if (w < 2 * NT) {
            int scale = (w >= NT) ? 1 : 0;
            int idx   = w - scale * NT;
            int b     = idx / TT;

            const float* cls = scale ? cls5 : cls4;
            const float* reg = scale ? reg5 : reg4;
            const int*   tc  = scale ? t5c  : t4c;
            const float* tb  = scale ? t5b  : t4b;
            const float* tm  = scale ? t5m  : t4m;
            uint32_t*    map = scale ? g_map5 : g_map4;
            const int S  = scale ? 40 : 80;
            const int HW = S * S;

            float mask = tm[idx];
            int   cid  = tc[idx];
            float bx = tb[idx*4+0], by = tb[idx*4+1];
            float bw = tb[idx*4+2], bh = tb[idx*4+3];

            float tx = bx * (float)S, ty = by * (float)S;
            float tw = bw * (float)S, th = bh * (float)S;
            int gx = (int)fminf(fmaxf(tx, 0.f), (float)(S-1));
            int gy = (int)fminf(fmaxf(ty, 0.f), (float)(S-1));
            int cell = gy * S + gx;

            const float* cbase = cls + (size_t)b * (NCLS+1) * HW + cell;
            const float* rbase = reg + (size_t)b * 4 * HW + cell;

            // focal loss over 80 classes, strided across the warp
            float fsum = 0.f;
            #pragma unroll
            for (int k = 0; k < 3; k++) {
                int c = lane + 32*k;
                if (c < NCLS) {
                    float x   = cbase[(size_t)(1 + c) * HW];
                    float tgt = (c == cid) ? 1.f : 0.f;
                    float bce = softplusf(x) - x * tgt;
                    float p   = 1.f / (1.f + __expf(-x));
                    float pt  = (tgt > 0.f) ? p : (1.f - p);
                    float om  = 1.f - pt;
                    fsum += 0.25f * om * om * bce;
                }
            }
            #pragma unroll
            for (int o = 16; o; o >>= 1) fsum += __shfl_xor_sync(0xffffffffu, fsum, o);

            if (lane == 0) {
                float rv0 = rbase[0];
                float rv1 = rbase[HW];
                float rv2 = rbase[2*HW];
                float rv3 = rbase[3*HW];
                float dx = 1.f / (1.f + __expf(-rv0));
                float dy = 1.f / (1.f + __expf(-rv1));
                float dw = __expf(fminf(fmaxf(rv2, -4.f), 4.f));
                float dh = __expf(fminf(fmaxf(rv3, -4.f), 4.f));
                float px = (float)gx + dx, py = (float)gy + dy;

                float d0 = (px - 0.5f*dw) - (tx - 0.5f*tw);
                float d1 = (py - 0.5f*dh) - (ty - 0.5f*th);
                float d2 = (px + 0.5f*dw) - (tx + 0.5f*tw);
                float d3 = (py + 0.5f*dh) - (ty + 0.5f*th);
                float sl1 = 0.f, a;
                a = fabsf(d0); sl1 += (a < 1.f) ? 0.5f*d0*d0 : a - 0.5f;
                a = fabsf(d1); sl1 += (a < 1.f) ? 0.5f*d1*d1 : a - 0.5f;
                a = fabsf(d2); sl1 += (a < 1.f) ? 0.5f*d2*d2 : a - 0.5f;
                a = fabsf(d3); sl1 += (a < 1.f) ? 0.5f*d3*d3 : a - 0.5f;
                sl1 *= 0.25f;

                float obj_t = cbase[0];

                atomicAdd(&sacc[0], sl1 * mask);
                atomicAdd(&sacc[1], softplusf(-obj_t) * mask);
                atomicAdd(&sacc[2], (fsum * (1.f / (float)NCLS)) * mask);
                atomicAdd(&sacc[3], mask);

                if (mask > 0.f) {
                    int gidx = b * HW + cell;
                    uint32_t old = atomicExch(&map[gidx], 1u);
                    if (old == 0u) {
                        // first distinct hit on this cell
                        atomicAdd(&sacc[6 + scale], softplusf(obj_t));
                        atomicAdd(&shit[scale], 1);
                        int pos = atomicAdd(&g_len, 1);
                        g_list[pos] = (uint32_t)gidx | ((uint32_t)scale << 31);
                    }
                }
            }
        }
    }

    // ---------------- background objectness: totals over ALL cells ----------------
    {
        int t      = blockIdx.x * BLK + tid;
        int stride = GRID * BLK;
        float s4 = 0.f, s5 = 0.f;
        const int N4 = BB * HW4, N5 = BB * HW5;
        for (int i = t; i < N4; i += stride) {
            int b = i / HW4, cell = i - b * HW4;
            s4 += softplusf(cls4[(size_t)b * (NCLS+1) * HW4 + cell]);
        }
        for (int i = t; i < N5; i += stride) {
            int b = i / HW5, cell = i - b * HW5;
            s5 += softplusf(cls5[(size_t)b * (NCLS+1) * HW5 + cell]);
        }
        #pragma unroll
        for (int o = 16; o; o >>= 1) {
            s4 += __shfl_xor_sync(0xffffffffu, s4, o);
            s5 += __shfl_xor_sync(0xffffffffu, s5, o);
        }
        if (lane == 0) {
            atomicAdd(&sacc[4], s4);
            atomicAdd(&sacc[5], s5);
        }
    }

    // ---------------- block -> global accumulation ----------------
    __syncthreads();
    if (tid < 8) atomicAdd(&g_accf[tid], sacc[tid]);
    if (tid < 2 && shit[tid]) atomicAdd(&g_hit[tid], shit[tid]);

    // ---------------- last block finishes up ----------------
    __threadfence();
    __syncthreads();
    if (tid == 0) {
        unsigned old = atomicAdd(&g_done, 1u);
        isLast = (old == (unsigned)(gridDim.x - 1));
    }
    __syncthreads();
    if (!isLast) return;

    // volatile reads (accumulators were written via L2 atomics)
    volatile float* vf = g_accf;
    volatile int*   vh = g_hit;
    volatile int*   vl = &g_len;

    int len = *vl;

    if (tid == 0) {
        float lb   = vf[0];
        float lo   = vf[1];
        float lc   = vf[2];
        float n    = vf[3];
        float tot4 = vf[4];
        float tot5 = vf[5];
        float cor4 = vf[6];
        float cor5 = vf[7];
        int   h4   = vh[0];
        int   h5   = vh[1];

        int bgc4 = BB * HW4 - h4;
        int bgc5 = BB * HW5 - h5;
        float bgs4 = tot4 - cor4;
        float bgs5 = tot5 - cor5;

        lo += 0.05f * ((bgc4 > 0) ? bgs4 / (float)(bgc4 > 1 ? bgc4 : 1) : 0.f);
        lo += 0.05f * ((bgc5 > 0) ? bgs5 / (float)(bgc5 > 1 ? bgc5 : 1) : 0.f);

        if (n > 0.f) {
            float dn = fmaxf(n, 1.f);
            lb /= dn;
            lc /= dn;
        }
        lo /= fmaxf(n, 1.f);

        out[0] = 2.0f * lb + 1.0f * lo + 0.5f * lc;
    }

    // cleanup: restore zero-state invariant for the next graph replay
    for (int i = tid; i < len; i += BLK) {
        uint32_t e = g_list[i];
        if (e & 0x80000000u) g_map5[e & 0x7fffffffu] = 0u;
        else                 g_map4[e]               = 0u;
    }
    if (tid < 8) g_accf[tid] = 0.f;
    if (tid < 2) g_hit[tid]  = 0;
    if (tid == 0) { g_len = 0; g_done = 0u; }
}

extern "C" void kernel_launch(void* const* d_in, const int* in_sizes, int n_in,
                              void* d_out, int out_size)
{
    const float* cls4 = (const float*)d_in[0];
    const float* reg4 = (const float*)d_in[1];
    const float* cls5 = (const float*)d_in[2];
    const float* reg5 = (const float*)d_in[3];
    const int*   t4c  = (const int*)  d_in[4];
    const float* t4b  = (const float*)d_in[5];
    const float* t4m  = (const float*)d_in[6];
    const int*   t5c  = (const int*)  d_in[7];
    const float* t5b  = (const float*)d_in[8];
    const float* t5m  = (const float*)d_in[9];
    float* out = (float*)d_out;

    k_all<<<GRID, BLK>>>(cls4, reg4, cls5, reg5,
                         t4c, t4b, t4m, t5c, t5b, t5m, out);
}

// round 3
// speedup vs baseline: 2.4389x; 1.0189x over previous
#include <cuda_runtime.h>
#include <cuda_bf16.h>
#include <math.h>
#include <stdint.h>

#define NCLS 80
#define BB   32
#define TT   64
#define HW4  (80*80)
#define HW5  (40*40)
#define NT   (BB*TT)          // targets per scale = 2048
#define GRID 592
#define BLK  256

// ---- persistent device scratch (zero-initialized at load; kernel restores zeros) ----
__device__ uint32_t g_map4[BB*HW4];
__device__ uint32_t g_map5[BB*HW5];
__device__ uint32_t g_list[2*NT];
// floats: 0 lb, 1 lo, 2 lc, 3 n, 4 tot4, 5 tot5, 6 corr4, 7 corr5
__device__ float    g_accf[8];
__device__ int      g_hit[2];
__device__ int      g_len;
__device__ unsigned g_done;

// fast softplus: max(x,0) + log(1 + exp(-|x|)), single EX2 + LG2
__device__ __forceinline__ float softplus_fast(float x) {
    float em = __expf(-fabsf(x));
    return fmaxf(x, 0.f) + __logf(1.f + em);
}

__global__ __launch_bounds__(BLK)
void k_all(const float* __restrict__ cls4, const float* __restrict__ reg4,
           const float* __restrict__ cls5, const float* __restrict__ reg5,
           const int*   __restrict__ t4c,  const float* __restrict__ t4b,
           const float* __restrict__ t4m,
           const int*   __restrict__ t5c,  const float* __restrict__ t5b,
           const float* __restrict__ t5m,
           float* __restrict__ out)
{
    __shared__ float sacc[8];
    __shared__ int   shit[2];
    __shared__ bool  isLast;

    int tid  = threadIdx.x;
    int lane = tid & 31;
    if (tid < 8) sacc[tid] = 0.f;
    if (tid < 2) shit[tid] = 0;
    __syncthreads();

    // ---------------- per-target losses (one warp per target) ----------------
    {
        int w = blockIdx.x * (BLK >> 5) + (tid >> 5);
        if (w < 2 * NT) {
            int scale = (w >= NT) ? 1 : 0;
            int idx   = w - scale * NT;
            int b     = idx / TT;

            const float* cls = scale ? cls5 : cls4;
            const float* reg = scale ? reg5 : reg4;
            const int*   tc  = scale ? t5c  : t4c;
            const float* tb  = scale ? t5b  : t4b;
            const float* tm  = scale ? t5m  : t4m;
            uint32_t*    map = scale ? g_map5 : g_map4;
            const int S  = scale ? 40 : 80;
            const int HW = S * S;

            float mask = tm[idx];
            int   cid  = tc[idx];
            float bx = tb[idx*4+0], by = tb[idx*4+1];
            float bw = tb[idx*4+2], bh = tb[idx*4+3];

            float tx = bx * (float)S, ty = by * (float)S;
            float tw = bw * (float)S, th = bh * (float)S;
            int gx = (int)fminf(fmaxf(tx, 0.f), (float)(S-1));
            int gy = (int)fminf(fmaxf(ty, 0.f), (float)(S-1));
            int cell = gy * S + gx;

            const float* cbase = cls + (size_t)b * (NCLS+1) * HW + cell;
            const float* rbase = reg + (size_t)b * 4 * HW + cell;

            // focal loss over 80 classes, strided across the warp
            float fsum = 0.f;
            #pragma unroll
            for (int k = 0; k < 3; k++) {
                int c = lane + 32*k;
                if (c < NCLS) {
                    float x  = cbase[(size_t)(1 + c) * HW];
                    float t  = (c == cid) ? 1.f : 0.f;
                    float em = __expf(-fabsf(x));
                    float L  = __logf(1.f + em);
                    float sp = fmaxf(x, 0.f) + L;             // softplus(x)
                    float r  = __fdividef(1.f, 1.f + em);
                    float s  = (x >= 0.f) ? r : 1.f - r;      // sigmoid(x)
                    float bce = sp - x * t;
                    float om  = (t > 0.f) ? (1.f - s) : s;    // 1 - pt
                    fsum += 0.25f * om * om * bce;
                }
            }
            #pragma unroll
            for (int o = 16; o; o >>= 1) fsum += __shfl_xor_sync(0xffffffffu, fsum, o);

            if (lane == 0) {
                float rv0 = rbase[0];
                float rv1 = rbase[HW];
                float rv2 = rbase[2*HW];
                float rv3 = rbase[3*HW];
                float dx = __fdividef(1.f, 1.f + __expf(-rv0));
                float dy = __fdividef(1.f, 1.f + __expf(-rv1));
                float dw = __expf(fminf(fmaxf(rv2, -4.f), 4.f));
                float dh = __expf(fminf(fmaxf(rv3, -4.f), 4.f));
                float px = (float)gx + dx, py = (float)gy + dy;

                float d0 = (px - 0.5f*dw) - (tx - 0.5f*tw);
                float d1 = (py - 0.5f*dh) - (ty - 0.5f*th);
                float d2 = (px + 0.5f*dw) - (tx + 0.5f*tw);
                float d3 = (py + 0.5f*dh) - (ty + 0.5f*th);
                float sl1 = 0.f, a;
                a = fabsf(d0); sl1 += (a < 1.f) ? 0.5f*d0*d0 : a - 0.5f;
                a = fabsf(d1); sl1 += (a < 1.f) ? 0.5f*d1*d1 : a - 0.5f;
                a = fabsf(d2); sl1 += (a < 1.f) ? 0.5f*d2*d2 : a - 0.5f;
                a = fabsf(d3); sl1 += (a < 1.f) ? 0.5f*d3*d3 : a - 0.5f;
                sl1 *= 0.25f;

                float obj_t = cbase[0];
                // softplus(-x) and softplus(x) share EX2/LG2
                float em = __expf(-fabsf(obj_t));
                float L  = __logf(1.f + em);
                float sp_neg = fmaxf(-obj_t, 0.f) + L;   // softplus(-obj_t)
                float sp_pos = fmaxf( obj_t, 0.f) + L;   // softplus(obj_t)

                atomicAdd(&sacc[0], sl1 * mask);
                atomicAdd(&sacc[1], sp_neg * mask);
                atomicAdd(&sacc[2], (fsum * (1.f / (float)NCLS)) * mask);
                atomicAdd(&sacc[3], mask);

                if (mask > 0.f) {
                    int gidx = b * HW + cell;
                    uint32_t old = atomicExch(&map[gidx], 1u);
                    if (old == 0u) {
                        atomicAdd(&sacc[6 + scale], sp_pos);
                        atomicAdd(&shit[scale], 1);
                        int pos = atomicAdd(&g_len, 1);
                        g_list[pos] = (uint32_t)gidx | ((uint32_t)scale << 31);
                    }
                }
            }
        }
    }

    // -------- background objectness totals over ALL cells (float4) --------
    {
        int t      = blockIdx.x * BLK + tid;
        int stride = GRID * BLK;
        float s4 = 0.f, s5 = 0.f;
        const int N4q = BB * HW4 / 4;   // float4 count
        const int N5q = BB * HW5 / 4;
        const int HW4q = HW4 / 4, HW5q = HW5 / 4;

        for (int i = t; i < N4q; i += stride) {
            int b = i / HW4q, c4 = i - b * HW4q;
            float4 v = *reinterpret_cast<const float4*>(
                cls4 + (size_t)b * (NCLS+1) * HW4 + (size_t)c4 * 4);
            s4 += softplus_fast(v.x) + softplus_fast(v.y)
                + softplus_fast(v.z) + softplus_fast(v.w);
        }
        for (int i = t; i < N5q; i += stride) {
            int b = i / HW5q, c5 = i - b * HW5q;
            float4 v = *reinterpret_cast<const float4*>(
                cls5 + (size_t)b * (NCLS+1) * HW5 + (size_t)c5 * 4);
            s5 += softplus_fast(v.x) + softplus_fast(v.y)
                + softplus_fast(v.z) + softplus_fast(v.w);
        }
        #pragma unroll
        for (int o = 16; o; o >>= 1) {
            s4 += __shfl_xor_sync(0xffffffffu, s4, o);
            s5 += __shfl_xor_sync(0xffffffffu, s5, o);
        }
        if (lane == 0) {
            atomicAdd(&sacc[4], s4);
            atomicAdd(&sacc[5], s5);
        }
    }

    // ---------------- block -> global accumulation ----------------
    __syncthreads();
    if (tid < 8) atomicAdd(&g_accf[tid], sacc[tid]);
    if (tid < 2 && shit[tid]) atomicAdd(&g_hit[tid], shit[tid]);

    __threadfence();
    __syncthreads();
    if (tid == 0) {
        unsigned old = atomicAdd(&g_done, 1u);
        isLast = (old == (unsigned)(gridDim.x - 1));
    }
    __syncthreads();
    if (!isLast) return;

    volatile float* vf = g_accf;
    volatile int*   vh = g_hit;
    volatile int*   vl = &g_len;
    int len = *vl;

    if (tid == 0) {
        float lb   = vf[0];
        float lo   = vf[1];
        float lc   = vf[2];
        float n    = vf[3];
        float bgs4 = vf[4] - vf[6];
        float bgs5 = vf[5] - vf[7];
        int   bgc4 = BB * HW4 - vh[0];
        int   bgc5 = BB * HW5 - vh[1];

        lo += 0.05f * ((bgc4 > 0) ? bgs4 / (float)(bgc4 > 1 ? bgc4 : 1) : 0.f);
        lo += 0.05f * ((bgc5 > 0) ? bgs5 / (float)(bgc5 > 1 ? bgc5 : 1) : 0.f);

        if (n > 0.f) {
            float dn = fmaxf(n, 1.f);
            lb /= dn;
            lc /= dn;
        }
        lo /= fmaxf(n, 1.f);

        out[0] = 2.0f * lb + 1.0f * lo + 0.5f * lc;
    }

    for (int i = tid; i < len; i += BLK) {
        uint32_t e = g_list[i];
        if (e & 0x80000000u) g_map5[e & 0x7fffffffu] = 0u;
        else                 g_map4[e]               = 0u;
    }
    if (tid < 8) g_accf[tid] = 0.f;
    if (tid < 2) g_hit[tid]  = 0;
    if (tid == 0) { g_len = 0; g_done = 0u; }
}

extern "C" void kernel_launch(void* const* d_in, const int* in_sizes, int n_in,
                              void* d_out, int out_size)
{
    const float* cls4 = (const float*)d_in[0];
    const float* reg4 = (const float*)d_in[1];
    const float* cls5 = (const float*)d_in[2];
    const float* reg5 = (const float*)d_in[3];
    const int*   t4c  = (const int*)  d_in[4];
    const float* t4b  = (const float*)d_in[5];
    const float* t4m  = (const float*)d_in[6];
    const int*   t5c  = (const int*)  d_in[7];
    const float* t5b  = (const float*)d_in[8];
    const float* t5m  = (const float*)d_in[9];
    float* out = (float*)d_out;

    k_all<<<GRID, BLK>>>(cls4, reg4, cls5, reg5,
                         t4c, t4b, t4m, t5c, t5b, t5m, out);
}

// round 6
// speedup vs baseline: 4.1312x; 1.6939x over previous
#include <cuda_runtime.h>
#include <cuda_bf16.h>
#include <math.h>
#include <stdint.h>

#define NCLS 80
#define BB   32
#define TT   64
#define HW4  (80*80)
#define HW5  (40*40)
#define NT   (BB*TT)          // 2048 targets per scale
#define GRID 512
#define BLK  256
#define N4Q  (BB*HW4/4)       // 51200 float4 quads, scale 4
#define N5Q  (BB*HW5/4)       // 12800 quads, scale 5

// ---- persistent device scratch (zero at load; epoch scheme avoids cleanup) ----
__device__ uint32_t g_map4[BB*HW4];
__device__ uint32_t g_map5[BB*HW5];
// 0 lb, 1 lo, 2 lc, 3 n, 4 tot4, 5 tot5, 6 corr4, 7 corr5
__device__ float    g_accf[8];
__device__ int      g_hit[2];
__device__ unsigned g_done;
__device__ uint32_t g_epoch;

__device__ __forceinline__ float softplus_fast(float x) {
    float em = __expf(-fabsf(x));
    return fmaxf(x, 0.f) + __logf(1.f + em);
}

// focal term for one logit
__device__ __forceinline__ float focal1(float x, bool pos) {
    float em = __expf(-fabsf(x));
    float L  = __logf(1.f + em);
    float sp = fmaxf(x, 0.f) + L;                 // softplus(x)
    float r  = __fdividef(1.f, 1.f + em);
    float s  = (x >= 0.f) ? r : 1.f - r;          // sigmoid(x)
    float bce = sp - (pos ? x : 0.f);
    float om  = pos ? (1.f - s) : s;              // 1 - pt
    return 0.25f * om * om * bce;
}

__global__ __launch_bounds__(BLK)
void k_all(const float* __restrict__ cls4, const float* __restrict__ reg4,
           const float* __restrict__ cls5, const float* __restrict__ reg5,
           const int*   __restrict__ t4c,  const float* __restrict__ t4b,
           const float* __restrict__ t4m,
           const int*   __restrict__ t5c,  const float* __restrict__ t5b,
           const float* __restrict__ t5m,
           float* __restrict__ out)
{
    __shared__ float sacc[8];
    __shared__ int   shit[2];
    __shared__ bool  isLast;

    const int tid  = threadIdx.x;
    const int lane = tid & 31;
    if (tid < 8) sacc[tid] = 0.f;
    if (tid < 2) shit[tid] = 0;
    __syncthreads();

    const uint32_t tag = g_epoch + 1u;

    // ================= stage 1: issue background float4 load (<=1/thread) ====
    const int t = blockIdx.x * BLK + tid;
    float4 bgv = make_float4(0.f, 0.f, 0.f, 0.f);
    int bsc = -1;
    if (t < N4Q) {
        int b = t / (HW4/4), c = t - b * (HW4/4);
        bgv = *reinterpret_cast<const float4*>(
            cls4 + (size_t)b * (NCLS+1) * HW4 + (size_t)c * 4);
        bsc = 0;
    } else if (t < N4Q + N5Q) {
        int q = t - N4Q;
        int b = q / (HW5/4), c = q - b * (HW5/4);
        bgv = *reinterpret_cast<const float4*>(
            cls5 + (size_t)b * (NCLS+1) * HW5 + (size_t)c * 4);
        bsc = 1;
    }

    // ================= stage 2: issue per-target box/mask/cid loads ==========
    const int  w   = blockIdx.x * (BLK >> 5) + (tid >> 5);
    const bool isT = (w < 2 * NT);
    int scale = 0, idx = 0, b = 0;
    float4 tbv = make_float4(0.f, 0.f, 0.f, 0.f);
    float  mask = 0.f;
    int    cid  = -1;
    const float* cls = cls4;
    const float* reg = reg4;
    uint32_t*    map = g_map4;
    int S = 80, HW = HW4;
    if (isT) {
        scale = (w >= NT) ? 1 : 0;
        idx   = w - (scale << 11);
        b     = idx >> 6;
        if (scale) {
            cls = cls5; reg = reg5; map = g_map5; S = 40; HW = HW5;
            tbv  = *reinterpret_cast<const float4*>(t5b + (size_t)idx * 4);
            mask = t5m[idx];  cid = t5c[idx];
        } else {
            tbv  = *reinterpret_cast<const float4*>(t4b + (size_t)idx * 4);
            mask = t4m[idx];  cid = t4c[idx];
        }
    }

    // ================= stage 3: consume bg while box loads fly ===============
    {
        float bs = (bsc >= 0)
            ? softplus_fast(bgv.x) + softplus_fast(bgv.y)
            + softplus_fast(bgv.z) + softplus_fast(bgv.w)
            : 0.f;
        #pragma unroll
        for (int o = 16; o; o >>= 1) bs += __shfl_xor_sync(0xffffffffu, bs, o);
        if (lane == 0 && bsc >= 0) atomicAdd(&sacc[4 + bsc], bs);
    }

    // ================= stage 4: gather wave + consume ========================
    if (isT) {
        float tx = tbv.x * (float)S, ty = tbv.y * (float)S;
        float tw = tbv.z * (float)S, th = tbv.w * (float)S;
        int gx = (int)fminf(fmaxf(tx, 0.f), (float)(S-1));
        int gy = (int)fminf(fmaxf(ty, 0.f), (float)(S-1));
        int cell = gy * S + gx;

        const float* cbase = cls + (size_t)b * (NCLS+1) * HW + cell;
        const float* rbase = reg + (size_t)b * 4 * HW + cell;

        // issue all 85 scattered loads in one wave (3 per lane)
        float x0 = cbase[(size_t)(1 + lane)  * HW];   // class lane
        float x1 = cbase[(size_t)(33 + lane) * HW];   // class lane+32
        const float* p2;
        if      (lane < 16)  p2 = cbase + (size_t)(65 + lane) * HW;   // class lane+64
        else if (lane == 16) p2 = cbase;                              // obj logit
        else if (lane <= 20) p2 = rbase + (size_t)(lane - 17) * HW;   // reg 0..3
        else                 p2 = cbase;                              // dup of obj (coalesced)
        float x2 = *p2;

        // focal math
        float fsum = focal1(x0, lane == cid) + focal1(x1, lane + 32 == cid);
        if (lane < 16) fsum += focal1(x2, lane + 64 == cid);
        #pragma unroll
        for (int o = 16; o; o >>= 1) fsum += __shfl_xor_sync(0xffffffffu, fsum, o);

        // aux values back from their lanes
        float obj_t = __shfl_sync(0xffffffffu, x2, 16);
        float rv0   = __shfl_sync(0xffffffffu, x2, 17);
        float rv1   = __shfl_sync(0xffffffffu, x2, 18);
        float rv2   = __shfl_sync(0xffffffffu, x2, 19);
        float rv3   = __shfl_sync(0xffffffffu, x2, 20);

        if (lane == 0) {
            float dx = __fdividef(1.f, 1.f + __expf(-rv0));
            float dy = __fdividef(1.f, 1.f + __expf(-rv1));
            float dw = __expf(fminf(fmaxf(rv2, -4.f), 4.f));
            float dh = __expf(fminf(fmaxf(rv3, -4.f), 4.f));
            float px = (float)gx + dx, py = (float)gy + dy;

            float d0 = (px - 0.5f*dw) - (tx - 0.5f*tw);
            float d1 = (py - 0.5f*dh) - (ty - 0.5f*th);
            float d2 = (px + 0.5f*dw) - (tx + 0.5f*tw);
            float d3 = (py + 0.5f*dh) - (ty + 0.5f*th);
            float sl1 = 0.f, a;
            a = fabsf(d0); sl1 += (a < 1.f) ? 0.5f*d0*d0 : a - 0.5f;
            a = fabsf(d1); sl1 += (a < 1.f) ? 0.5f*d1*d1 : a - 0.5f;
            a = fabsf(d2); sl1 += (a < 1.f) ? 0.5f*d2*d2 : a - 0.5f;
            a = fabsf(d3); sl1 += (a < 1.f) ? 0.5f*d3*d3 : a - 0.5f;
            sl1 *= 0.25f;

            float em = __expf(-fabsf(obj_t));
            float L  = __logf(1.f + em);
            float sp_neg = fmaxf(-obj_t, 0.f) + L;   // softplus(-obj)
            float sp_pos = fmaxf( obj_t, 0.f) + L;   // softplus(+obj)

            atomicAdd(&sacc[0], sl1 * mask);
            atomicAdd(&sacc[1], sp_neg * mask);
            atomicAdd(&sacc[2], (fsum * (1.f / (float)NCLS)) * mask);
            atomicAdd(&sacc[3], mask);

            if (mask > 0.f) {
                int gidx = b * HW + cell;
                uint32_t old = atomicExch(&map[gidx], tag);
                if (old != tag) {                    // first hit this replay
                    atomicAdd(&sacc[6 + scale], sp_pos);
                    atomicAdd(&shit[scale], 1);
                }
            }
        }
    }

    // ================= block -> global, last-block finalize ==================
    __syncthreads();
    if (tid < 8) atomicAdd(&g_accf[tid], sacc[tid]);
    if (tid < 2 && shit[tid]) atomicAdd(&g_hit[tid], shit[tid]);

    __threadfence();
    __syncthreads();
    if (tid == 0) {
        unsigned old = atomicAdd(&g_done, 1u);
        isLast = (old == (unsigned)(GRID - 1));
    }
    __syncthreads();
    if (!isLast) return;

    if (tid == 0) {
        volatile float* vf = g_accf;
        volatile int*   vh = g_hit;

        float lb   = vf[0];
        float lo   = vf[1];
        float lc   = vf[2];
        float n    = vf[3];
        float bgs4 = vf[4] - vf[6];
        float bgs5 = vf[5] - vf[7];
        int   bgc4 = BB * HW4 - vh[0];
        int   bgc5 = BB * HW5 - vh[1];

        lo += 0.05f * ((bgc4 > 0) ? bgs4 / (float)(bgc4 > 1 ? bgc4 : 1) : 0.f);
        lo += 0.05f * ((bgc5 > 0) ? bgs5 / (float)(bgc5 > 1 ? bgc5 : 1) : 0.f);

        if (n > 0.f) {
            float dn = fmaxf(n, 1.f);
            lb /= dn;
            lc /= dn;
        }
        lo /= fmaxf(n, 1.f);

        out[0] = 2.0f * lb + 1.0f * lo + 0.5f * lc;

        // reset for next replay (maps persist; epoch bump invalidates them)
        #pragma unroll
        for (int i = 0; i < 8; i++) g_accf[i] = 0.f;
        g_hit[0] = 0; g_hit[1] = 0;
        g_done = 0u;
        g_epoch = tag;
    }
}

extern "C" void kernel_launch(void* const* d_in, const int* in_sizes, int n_in,
                              void* d_out, int out_size)
{
    const float* cls4 = (const float*)d_in[0];
    const float* reg4 = (const float*)d_in[1];
    const float* cls5 = (const float*)d_in[2];
    const float* reg5 = (const float*)d_in[3];
    const int*   t4c  = (const int*)  d_in[4];
    const float* t4b  = (const float*)d_in[5];
    const float* t4m  = (const float*)d_in[6];
    const int*   t5c  = (const int*)  d_in[7];
    const float* t5b  = (const float*)d_in[8];
    const float* t5m  = (const float*)d_in[9];
    float* out = (float*)d_out;

    k_all<<<GRID, BLK>>>(cls4, reg4, cls5, reg5,
                         t4c, t4b, t4m, t5c, t5b, t5m, out);
}